// round 9
// baseline (speedup 1.0000x reference)
#include <cuda_runtime.h>
#include <cstdint>

// Shapes are fixed by the problem: B=4, N=M=8192, D=3.
#define NB 4
#define ND 8192
#define TOTAL (2 * NB * ND)   // 65536 (dir, batch, point) slots

// Scratch (device globals — no allocation allowed).
__device__ unsigned g_keys[TOTAL];  // (distbits & 0xFFFFE000) | idx(13b)
__device__ unsigned g_cnt[TOTAL];   // nn target counts per direction

// ---------------- packed f32x2 helpers ----------------
__device__ __forceinline__ unsigned long long pack2(float lo, float hi) {
    unsigned long long r;
    asm("mov.b64 %0, {%1, %2};" : "=l"(r) : "r"(__float_as_uint(lo)), "r"(__float_as_uint(hi)));
    return r;
}
__device__ __forceinline__ unsigned long long fma2(unsigned long long a,
                                                   unsigned long long b,
                                                   unsigned long long c) {
    unsigned long long d;
    asm("fma.rn.f32x2 %0, %1, %2, %3;" : "=l"(d) : "l"(a), "l"(b), "l"(c));
    return d;
}
__device__ __forceinline__ unsigned long long add2(unsigned long long a,
                                                   unsigned long long b) {
    unsigned long long d;
    asm("add.rn.f32x2 %0, %1, %2;" : "=l"(d) : "l"(a), "l"(b));
    return d;
}

// ---------------- init: clear scratch + output ----------------
__global__ void init_k(float* out) {
    int i = blockIdx.x * blockDim.x + threadIdx.x;
    if (i < TOTAL) {
        g_keys[i] = 0xFFFFFFFFu;
        g_cnt[i]  = 0u;
    }
    if (i == 0) out[0] = 0.0f;
}

// ---------------- brute-force NN (both directions fused) ----------------
// grid = 2(dir) * 4(batch) * 32(src chunks of 256) * 4(M splits of 2048) = 1024 blocks
// block = 256 threads, one src point per thread; scans 2048 opposite points
// in 4 shared tiles of 512 points. Tile layout per entry e (2 points a,c):
//   tileF[2e]   = (-2a0, -2c0, -2a1, -2c1)
//   tileF[2e+1] = (-2a2, -2c2,  aa ,  cc )
// read back as ulonglong2 pairs -> direct f32x2 operands, no repacking movs.
__global__ __launch_bounds__(256, 1)
void nn_k(const float* __restrict__ xg, const float* __restrict__ yg) {
    __shared__ float4 tileF[512];
    const ulonglong2* tp = reinterpret_cast<const ulonglong2*>(tileF);

    unsigned bid   = blockIdx.x;
    unsigned split = bid & 3u;  bid >>= 2;
    unsigned chunk = bid & 31u; bid >>= 5;
    unsigned b     = bid & 3u;  bid >>= 2;
    unsigned dir   = bid;       // 0: x->y, 1: y->x

    const float* src = dir ? yg : xg;
    const float* tgt = dir ? xg : yg;

    unsigned p = chunk * 256u + threadIdx.x;
    const float* sp = src + ((size_t)b * ND + p) * 3u;
    float sx0 = sp[0], sx1 = sp[1], sx2 = sp[2];
    float xx  = sx0 * sx0 + sx1 * sx1 + sx2 * sx2;
    unsigned long long x0p = pack2(sx0, sx0);
    unsigned long long x1p = pack2(sx1, sx1);
    unsigned long long x2p = pack2(sx2, sx2);
    unsigned long long xxp = pack2(xx, xx);

    unsigned mask = 0xFFFFE000u;        // keep sign+exp+10 mantissa bits
    asm("" : "+r"(mask));               // force into a register -> single LOP3

    unsigned best = 0xFFFFFFFFu;

    #pragma unroll 1
    for (int t = 0; t < 4; ++t) {
        unsigned jbase = split * 2048u + (unsigned)t * 512u;
        {   // cooperative tile load: thread i handles points 2i, 2i+1
            int i = threadIdx.x;
            const float* q = tgt + ((size_t)b * ND + jbase + 2u * i) * 3u;
            float a0 = q[0], a1 = q[1], a2 = q[2];
            float c0 = q[3], c1 = q[4], c2 = q[5];
            tileF[2 * i]     = make_float4(-2.f * a0, -2.f * c0, -2.f * a1, -2.f * c1);
            tileF[2 * i + 1] = make_float4(-2.f * a2, -2.f * c2,
                                           a0 * a0 + a1 * a1 + a2 * a2,
                                           c0 * c0 + c1 * c1 + c2 * c2);
        }
        __syncthreads();

        unsigned tileBest = 0xFFFFFFFFu;
        #pragma unroll 1
        for (int eo = 0; eo < 16; ++eo) {
            const ulonglong2* te = tp + eo * 32;
            unsigned inner = 0xFFFFFFFFu;
            #pragma unroll
            for (int ei = 0; ei < 16; ++ei) {
                ulonglong2 q0 = te[2 * ei];       // (-2y0 pair, -2y1 pair)
                ulonglong2 q1 = te[2 * ei + 1];   // (-2y2 pair,  yy  pair)
                // d = xx + yy - 2*x.y  (two points per op)
                unsigned long long d2 =
                    fma2(x0p, q0.x, fma2(x1p, q0.y, fma2(x2p, q1.x, add2(q1.y, xxp))));
                unsigned lo = (unsigned)(d2 & 0xFFFFFFFFull);
                unsigned hi = (unsigned)(d2 >> 32);
                unsigned klo = (lo & mask) | (unsigned)(2 * ei);
                unsigned khi = (hi & mask) | (unsigned)(2 * ei + 1);
                inner = min(inner, klo);
                inner = min(inner, khi);
            }
            tileBest = min(tileBest, inner | (unsigned)(eo << 5));
        }
        best = min(best, tileBest | jbase);
        __syncthreads();
    }
    atomicMin(&g_keys[(dir * NB + b) * ND + p], best);
}

// ---------------- density counts ----------------
__global__ void cnt_k() {
    int i = blockIdx.x * blockDim.x + threadIdx.x;
    if (i < TOTAL) {
        unsigned k = g_keys[i];
        atomicAdd(&g_cnt[((unsigned)i & ~(unsigned)(ND - 1)) | (k & (unsigned)(ND - 1))], 1u);
    }
}

// ---------------- final loss: exact dist recompute + weighted mean ----------------
__global__ __launch_bounds__(256)
void loss_k(const float* __restrict__ xg, const float* __restrict__ yg,
            float* __restrict__ out) {
    __shared__ float red[256];
    int i = blockIdx.x * blockDim.x + threadIdx.x;   // < 65536 exactly

    unsigned dirb = (unsigned)i >> 13;               // dir*4 + b
    unsigned p    = (unsigned)i & (ND - 1);
    unsigned dir  = dirb >> 2;
    unsigned b    = dirb & 3u;

    const float* src = dir ? yg : xg;
    const float* tg  = dir ? xg : yg;

    unsigned k   = g_keys[i];
    unsigned idx = k & (unsigned)(ND - 1);
    unsigned c   = g_cnt[((unsigned)i & ~(unsigned)(ND - 1)) | idx];

    const float* sp = src + ((size_t)b * ND + p) * 3u;
    const float* tp = tg  + ((size_t)b * ND + idx) * 3u;
    float sx0 = sp[0], sx1 = sp[1], sx2 = sp[2];
    float ty0 = tp[0], ty1 = tp[1], ty2 = tp[2];

    float xx  = sx0 * sx0 + sx1 * sx1 + sx2 * sx2;
    float yy  = ty0 * ty0 + ty1 * ty1 + ty2 * ty2;
    float dot = sx0 * ty0 + sx1 * ty1 + sx2 * ty2;
    float d   = xx - 2.0f * dot + yy;                // same expanded form as reference

    float w    = 1.0f / ((float)c + 1e-6f);          // N_LAMBDA = 1
    float term = 1.0f - expf(-d * 1000.0f) * w;      // ALPHA = 1000

    red[threadIdx.x] = term;
    __syncthreads();
    #pragma unroll
    for (int s = 128; s > 0; s >>= 1) {
        if (threadIdx.x < s) red[threadIdx.x] += red[threadIdx.x + s];
        __syncthreads();
    }
    if (threadIdx.x == 0)
        atomicAdd(out, red[0] * (1.0f / (float)TOTAL));  // mean_b((l1+l2)/2)
}

extern "C" void kernel_launch(void* const* d_in, const int* in_sizes, int n_in,
                              void* d_out, int out_size) {
    const float* x = (const float*)d_in[0];
    const float* y = (const float*)d_in[1];
    float* out = (float*)d_out;

    init_k<<<(TOTAL + 255) / 256, 256>>>(out);
    nn_k<<<2 * NB * 32 * 4, 256>>>(x, y);      // 1024 blocks
    cnt_k<<<(TOTAL + 255) / 256, 256>>>();
    loss_k<<<TOTAL / 256, 256>>>(x, y, out);
}